// round 14
// baseline (speedup 1.0000x reference)
#include <cuda_runtime.h>

// y = (U kron I2) @ x, U[i,i+1] = sqrt(i+1)
// x: (2D, B) fp32, D=4096, B=4096.
// out[r] = sqrt(r/2 + 1) * x[r+2] (rowwise), last two rows zero.
//
// FINAL (converged, R13-confirmed): bench 43.49-43.52us across three
// independent runs of distinct geometries — pinned at the GB300 mixed
// rd+wr HBM stream ceiling (71.6-74.2% DRAM, ~5.7-5.9 TB/s of 8 TB/s
// spec; remainder is read/write bus turnaround, not kernel-controllable).
// Traffic (128 MiB read + 128 MiB write) is irreducible; SM-side cost is
// negligible (issue 6%, alu 1%). No further levers exist within harness
// constraints (L2 persistence API forbidden; TMA shares the same LTS cap).
//
// Geometry: one block per row pair (rows 2i, 2i+1 share coef = sqrt(i+1)).
// 256 threads x 8 front-batched float4 = 32 KiB/block. Streaming (.cs)
// loads/stores — zero reuse.

static constexpr int D = 4096;
static constexpr int B4 = 4096 / 4;          // 1024 float4 per row
static constexpr int PAIR4 = 2 * B4;         // 2048 float4 per row pair
static constexpr int NPAIRS = D;             // 4096 blocks
static constexpr int LAST_PAIR = D - 1;      // pair i = D-1 is all zero

__global__ void __launch_bounds__(256) destroy_kernel(const float4* __restrict__ in,
                                                      float4* __restrict__ out) {
    const int pair = blockIdx.x;
    const int tid = threadIdx.x;
    float4* opair = out + (size_t)pair * PAIR4;

    if (pair < LAST_PAIR) {
        const float coef = sqrtf((float)(pair + 1));
        const float4* ipair = in + (size_t)(pair + 1) * PAIR4;  // rows shifted by 2

        float4 v[8];
#pragma unroll
        for (int k = 0; k < 8; k++) {
            v[k] = __ldcs(ipair + tid + k * 256);
            v[k].x *= coef; v[k].y *= coef; v[k].z *= coef; v[k].w *= coef;
        }

#pragma unroll
        for (int k = 0; k < 8; k++)
            __stcs(opair + tid + k * 256, v[k]);
    } else {
        const float4 z = make_float4(0.f, 0.f, 0.f, 0.f);
#pragma unroll
        for (int k = 0; k < 8; k++)
            __stcs(opair + tid + k * 256, z);
    }
}

extern "C" void kernel_launch(void* const* d_in, const int* in_sizes, int n_in,
                              void* d_out, int out_size) {
    const float4* in = (const float4*)d_in[0];
    float4* out = (float4*)d_out;
    destroy_kernel<<<NPAIRS, 256>>>(in, out);
}

// round 16
// speedup vs baseline: 1.0471x; 1.0471x over previous
#include <cuda_runtime.h>
#include <cstdint>

// y = (U kron I2) @ x, U[i,i+1] = sqrt(i+1)
// x: (2D, B) fp32, D=4096, B=4096.
// out[r] = sqrt(r/2 + 1) * x[r+2] (rowwise), last two rows zero.
//
// Row-pair geometry (best measured: 43.49us bench) + Blackwell 256-bit
// global accesses (ld/st.global.{cs}.v8.f32, sm_100+): halves LDG/STG
// count per byte vs float4. DRAM-stream-bound either way (~73% of spec,
// mixed rd+wr ceiling); this trims LSU issue / L1tex wavefronts.
//
// One block per row pair (rows 2i, 2i+1 share coef = sqrt(i+1)).
// 256 threads x 4 x 32B = 32 KiB per block.

static constexpr int D = 4096;
static constexpr int B_ELEMS = 4096;               // floats per row
static constexpr int PAIR_ELEMS = 2 * B_ELEMS;     // 8192 floats per row pair
static constexpr int NPAIRS = D;                   // 4096 blocks
static constexpr int LAST_PAIR = D - 1;            // pair i = D-1 is all zero

__device__ __forceinline__ void ld_v8_cs(const float* p, float* v) {
    asm volatile("ld.global.cs.v8.f32 {%0,%1,%2,%3,%4,%5,%6,%7}, [%8];"
                 : "=f"(v[0]), "=f"(v[1]), "=f"(v[2]), "=f"(v[3]),
                   "=f"(v[4]), "=f"(v[5]), "=f"(v[6]), "=f"(v[7])
                 : "l"(p));
}

__device__ __forceinline__ void st_v8_cs(float* p, const float* v) {
    asm volatile("st.global.cs.v8.f32 [%0], {%1,%2,%3,%4,%5,%6,%7,%8};"
                 :: "l"(p),
                    "f"(v[0]), "f"(v[1]), "f"(v[2]), "f"(v[3]),
                    "f"(v[4]), "f"(v[5]), "f"(v[6]), "f"(v[7])
                 : "memory");
}

__global__ void __launch_bounds__(256) destroy_kernel(const float* __restrict__ in,
                                                      float* __restrict__ out) {
    const int pair = blockIdx.x;
    const int tid = threadIdx.x;
    float* opair = out + (size_t)pair * PAIR_ELEMS;

    if (pair < LAST_PAIR) {
        const float coef = sqrtf((float)(pair + 1));
        const float* ipair = in + (size_t)(pair + 1) * PAIR_ELEMS;  // shift by 2 rows

        // 4 sweeps: 256 threads x 8 floats = 2048 floats per sweep.
        float v[4][8];
#pragma unroll
        for (int k = 0; k < 4; k++)
            ld_v8_cs(ipair + tid * 8 + k * 2048, v[k]);

#pragma unroll
        for (int k = 0; k < 4; k++)
#pragma unroll
            for (int j = 0; j < 8; j++)
                v[k][j] *= coef;

#pragma unroll
        for (int k = 0; k < 4; k++)
            st_v8_cs(opair + tid * 8 + k * 2048, v[k]);
    } else {
        float z[8] = {0.f, 0.f, 0.f, 0.f, 0.f, 0.f, 0.f, 0.f};
#pragma unroll
        for (int k = 0; k < 4; k++)
            st_v8_cs(opair + tid * 8 + k * 2048, z);
    }
}

extern "C" void kernel_launch(void* const* d_in, const int* in_sizes, int n_in,
                              void* d_out, int out_size) {
    const float* in = (const float*)d_in[0];
    float* out = (float*)d_out;
    destroy_kernel<<<NPAIRS, 256>>>(in, out);
}